// round 11
// baseline (speedup 1.0000x reference)
#include <cuda_runtime.h>

#define BB 8
#define TT 128
#define DD 256

__device__ __forceinline__ float ex2f(float x) {
    float y; asm("ex2.approx.f32 %0, %1;" : "=f"(y) : "f"(x)); return y;
}

// One block per (b,t). Thread tid = (rp, cg): cols 8cg..8cg+7, rows 32rp..32rp+31.
// Scalar math only: per 8 entries = 1 LDS + 8 FMUL + 8 EX2 + 8 FADD + 7 FADD
// + 1 SHFL + 1 FADD + 1 predicated STS. Row partials pair-combined across
// adjacent lanes to halve s_rp (smem 26KB -> 6-8 blocks/SM).
__global__ __launch_bounds__(DD, 6) void attn_fused_kernel(
    const float* __restrict__ dec_t,   // [B, D]
    const float* __restrict__ enc_out, // [B, T, D]
    float* __restrict__ out            // [B, D], pre-zeroed
) {
    __shared__ float s_dec[DD];          // dec * log2e
    __shared__ float s_rp[DD][17];       // row partials, 16 per row (pair-combined), pad 17
    __shared__ float s_cp[8][DD];        // colsum partials per row-part

    const int bt  = blockIdx.x;          // b*T + t
    const int b   = bt >> 7;
    const int tid = threadIdx.x;
    const int cg  = tid & 31;            // col group (8 cols), = lane
    const int rp  = tid >> 5;            // row part (32 rows), = warp

    const float L2E = 1.4426950408889634f;
    s_dec[tid] = dec_t[b * DD + tid] * L2E;

    const float4 xa = *(const float4*)(enc_out + bt * DD + cg * 8);
    const float4 xb = *(const float4*)(enc_out + bt * DD + cg * 8 + 4);
    const float x0 = xa.x, x1 = xa.y, x2 = xa.z, x3 = xa.w;
    const float x4 = xb.x, x5 = xb.y, x6 = xb.z, x7 = xb.w;

    __syncthreads();

    float c0 = 0.f, c1 = 0.f, c2 = 0.f, c3 = 0.f;
    float c4 = 0.f, c5 = 0.f, c6 = 0.f, c7 = 0.f;

    const int pbase = rp * 32;
#pragma unroll 8
    for (int i = 0; i < 32; i++) {
        const float d  = s_dec[pbase + i];       // warp-uniform broadcast LDS
        const float e0 = ex2f(d * x0);
        const float e1 = ex2f(d * x1);
        const float e2 = ex2f(d * x2);
        const float e3 = ex2f(d * x3);
        const float e4 = ex2f(d * x4);
        const float e5 = ex2f(d * x5);
        const float e6 = ex2f(d * x6);
        const float e7 = ex2f(d * x7);
        c0 += e0; c1 += e1; c2 += e2; c3 += e3;
        c4 += e4; c5 += e5; c6 += e6; c7 += e7;
        float r8 = ((e0 + e1) + (e2 + e3)) + ((e4 + e5) + (e6 + e7));
        r8 += __shfl_xor_sync(0xffffffffu, r8, 1, 32);      // 16-col partial
        if ((cg & 1) == 0)
            s_rp[pbase + i][cg >> 1] = r8;       // 16 distinct banks, no conflict
    }

    // spill colsum partials (2x STS.128)
    *(float4*)&s_cp[rp][cg * 8]     = make_float4(c0, c1, c2, c3);
    *(float4*)&s_cp[rp][cg * 8 + 4] = make_float4(c4, c5, c6, c7);
    __syncthreads();

    // rowsum of row tid (same thread outputs column q = tid)
    float rs = 0.f;
#pragma unroll
    for (int j = 0; j < 16; j++) rs += s_rp[tid][j];   // stride 17 -> conflict-free

    float cs = 0.f;
#pragma unroll
    for (int r = 0; r < 8; r++) cs += s_cp[r][tid];    // lane-distinct banks

    const float x = enc_out[bt * DD + tid];
    atomicAdd(&out[b * DD + tid], __fdividef(x * cs, rs));
}

extern "C" void kernel_launch(void* const* d_in, const int* in_sizes, int n_in,
                              void* d_out, int out_size) {
    const float* dec_t   = (const float*)d_in[0];
    const float* enc_out = (const float*)d_in[1];
    if (n_in >= 2 && in_sizes[0] == BB * TT * DD && in_sizes[1] == BB * DD) {
        dec_t   = (const float*)d_in[1];
        enc_out = (const float*)d_in[0];
    }
    float* out = (float*)d_out;

    cudaMemsetAsync(out, 0, BB * DD * sizeof(float), 0);
    attn_fused_kernel<<<BB * TT, DD>>>(dec_t, enc_out, out);
}

// round 12
// speedup vs baseline: 1.1180x; 1.1180x over previous
#include <cuda_runtime.h>

#define BB 8
#define TT 128
#define DD 256

typedef unsigned long long u64;

__device__ __forceinline__ float ex2f(float x) {
    float y; asm("ex2.approx.f32 %0, %1;" : "=f"(y) : "f"(x)); return y;
}
// packed add on float2 (register pairs)
__device__ __forceinline__ float2 padd2(float2 a, float2 b) {
    float2 r;
    asm("add.rn.f32x2 %0, %1, %2;"
        : "=l"(*(u64*)&r) : "l"(*(u64*)&a), "l"(*(u64*)&b));
    return r;
}

// One block per (b,t). Thread tid = (rp, cg): cols 8cg..8cg+7, rows 32rp..32rp+31.
// Fully unrolled 32-row body; per 8 entries: 1 LDS + 8 FMUL + 8 EX2 + 4 packed
// col-adds + 3 packed tree-adds + 1 FADD + 1 SHFL + 1 FADD + 1 pred-STS.
__global__ __launch_bounds__(DD) void attn_fused_kernel(
    const float* __restrict__ dec_t,   // [B, D]
    const float* __restrict__ enc_out, // [B, T, D]
    float* __restrict__ out            // [B, D], pre-zeroed
) {
    __shared__ float s_dec[DD];          // dec * log2e
    __shared__ float s_rp[DD][17];       // row partials (16 per row, lane-pair combined)
    __shared__ float s_cp[8][DD];        // colsum partials per row-part

    const int bt  = blockIdx.x;          // b*T + t
    const int b   = bt >> 7;
    const int tid = threadIdx.x;
    const int cg  = tid & 31;            // col group (8 cols) = lane
    const int rp  = tid >> 5;            // row part (32 rows) = warp

    const float L2E = 1.4426950408889634f;
    s_dec[tid] = dec_t[b * DD + tid] * L2E;

    const float4 xa = *(const float4*)(enc_out + bt * DD + cg * 8);
    const float4 xb = *(const float4*)(enc_out + bt * DD + cg * 8 + 4);

    __syncthreads();

    float2 c01 = make_float2(0.f, 0.f), c23 = make_float2(0.f, 0.f);
    float2 c45 = make_float2(0.f, 0.f), c67 = make_float2(0.f, 0.f);

    const float* dbase = &s_dec[rp * 32];
    float* rbase = &s_rp[rp * 32][cg >> 1];
    const bool wlane = ((cg & 1) == 0);

#pragma unroll
    for (int i = 0; i < 32; i++) {
        const float d = dbase[i];               // warp-uniform, immediate offset
        float2 e01, e23, e45, e67;
        e01.x = ex2f(d * xa.x);  e01.y = ex2f(d * xa.y);
        e23.x = ex2f(d * xa.z);  e23.y = ex2f(d * xa.w);
        e45.x = ex2f(d * xb.x);  e45.y = ex2f(d * xb.y);
        e67.x = ex2f(d * xb.z);  e67.y = ex2f(d * xb.w);
        c01 = padd2(c01, e01);   c23 = padd2(c23, e23);
        c45 = padd2(c45, e45);   c67 = padd2(c67, e67);
        const float2 sa = padd2(padd2(e01, e23), padd2(e45, e67));
        float r8 = sa.x + sa.y;
        r8 += __shfl_xor_sync(0xffffffffu, r8, 1, 32);
        if (wlane) rbase[i * 17] = r8;           // immediate-offset STS, 16 banks
    }

    // spill colsum partials (2x STS.128)
    *(float4*)&s_cp[rp][cg * 8]     = make_float4(c01.x, c01.y, c23.x, c23.y);
    *(float4*)&s_cp[rp][cg * 8 + 4] = make_float4(c45.x, c45.y, c67.x, c67.y);
    __syncthreads();

    // rowsum of row tid (same thread outputs column q = tid)
    float rs = 0.f;
#pragma unroll
    for (int j = 0; j < 16; j++) rs += s_rp[tid][j];   // stride-17: conflict-free

    float cs = 0.f;
#pragma unroll
    for (int r = 0; r < 8; r++) cs += s_cp[r][tid];

    const float x = enc_out[bt * DD + tid];
    atomicAdd(&out[b * DD + tid], __fdividef(x * cs, rs));
}

extern "C" void kernel_launch(void* const* d_in, const int* in_sizes, int n_in,
                              void* d_out, int out_size) {
    const float* dec_t   = (const float*)d_in[0];
    const float* enc_out = (const float*)d_in[1];
    if (n_in >= 2 && in_sizes[0] == BB * TT * DD && in_sizes[1] == BB * DD) {
        dec_t   = (const float*)d_in[1];
        enc_out = (const float*)d_in[0];
    }
    float* out = (float*)d_out;

    cudaMemsetAsync(out, 0, BB * DD * sizeof(float), 0);
    attn_fused_kernel<<<BB * TT, DD>>>(dec_t, enc_out, out);
}